// round 1
// baseline (speedup 1.0000x reference)
#include <cuda_runtime.h>
#include <cstdint>

// Problem constants (fixed by the reference)
#define NQ      64      // qubits
#define NS      4096    // samples per unique circuit
#define NU      256     // unique circuits
#define NB      1024    // batch size (output rows)
#define CHUNKS  (NS / 32)      // 128 chunks of 32 samples
#define THREADS 256
#define NWARPS  (THREADS / 32) // 8
#define CH_PER_WARP (CHUNKS / NWARPS) // 16

// Per-circuit mean energies, shared between the two launches.
__device__ float g_unique[NU];

// One block per unique circuit.
// Phase 1: stream 1 MB of int32 bitstrings, pack each sample into a 64-bit
//          mask, bit-transpose via warp ballots into per-qubit bit columns.
// Phase 2: XOR-popcount pair counting over the bit columns -> exact
//          correlation counts; fold with K and bias; block-reduce.
__global__ void __launch_bounds__(THREADS)
energy_kernel(const int* __restrict__ samples,
              const float* __restrict__ bias,
              const float* __restrict__ kern)
{
    __shared__ uint32_t col[CHUNKS][NQ];   // [chunk][qubit] : 32 KB
    __shared__ float red[THREADS];

    const int tid  = threadIdx.x;
    const int lane = tid & 31;
    const int w    = tid >> 5;
    const int c    = blockIdx.x;

    const int* base = samples + (size_t)c * (size_t)(NS * NQ);

    // ---------------- Phase 1: pack + bit-transpose ----------------
    #pragma unroll 1
    for (int k = 0; k < CH_PER_WARP; k++) {
        const int ch = w * CH_PER_WARP + k;
        const int s  = ch * 32 + lane;             // sample index
        const uint4* row = (const uint4*)(base + (size_t)s * NQ);

        // Values are exactly 0/1 int32 -> nibble via pure adds/shifts.
        uint32_t lo = 0u, hi = 0u;
        #pragma unroll
        for (int i = 0; i < 8; i++) {
            uint4 v = row[i];
            uint32_t nib = v.x + (v.y << 1) + (v.z << 2) + (v.w << 3);
            lo |= nib << (4 * i);
        }
        #pragma unroll
        for (int i = 8; i < 16; i++) {
            uint4 v = row[i];
            uint32_t nib = v.x + (v.y << 1) + (v.z << 2) + (v.w << 3);
            hi |= nib << (4 * (i - 8));
        }

        // 64 ballots: column q over the 32 samples of this chunk.
        #pragma unroll
        for (int q = 0; q < 32; q++) {
            uint32_t b = __ballot_sync(0xffffffffu, (lo >> q) & 1u);
            if (lane == q) col[ch][q] = b;
        }
        #pragma unroll
        for (int q = 0; q < 32; q++) {
            uint32_t b = __ballot_sync(0xffffffffu, (hi >> q) & 1u);
            if (lane == q) col[ch][32 + q] = b;
        }
    }
    __syncthreads();

    // ---------------- Phase 2: pair counting ----------------
    // Thread owns the 4x4 tile (q0..q0+3) x (r0..r0+3) of the FULL 64x64
    // ordered-pair matrix. Diagonal pairs give XOR count 0 -> C_qq = 1,
    // exactly what the formula needs. No special cases.
    const int q0 = (tid >> 4) << 2;   // 0,4,...,60
    const int r0 = (tid & 15) << 2;

    int cnt[4][4];
    #pragma unroll
    for (int i = 0; i < 4; i++)
        #pragma unroll
        for (int j = 0; j < 4; j++)
            cnt[i][j] = 0;

    #pragma unroll 4
    for (int ch = 0; ch < CHUNKS; ch++) {
        const uint4 a4 = *(const uint4*)&col[ch][q0];
        const uint4 b4 = *(const uint4*)&col[ch][r0];
        const uint32_t a[4] = {a4.x, a4.y, a4.z, a4.w};
        const uint32_t b[4] = {b4.x, b4.y, b4.z, b4.w};
        #pragma unroll
        for (int i = 0; i < 4; i++)
            #pragma unroll
            for (int j = 0; j < 4; j++)
                cnt[i][j] += __popc(a[i] ^ b[j]);
    }

    // Fold K: sum over tile of K[q][r] * (NS - 2*XorCount). K loads hit L2.
    float p = 0.f;
    #pragma unroll
    for (int i = 0; i < 4; i++)
        #pragma unroll
        for (int j = 0; j < 4; j++)
            p += kern[(q0 + i) * NQ + (r0 + j)] * (float)(NS - 2 * cnt[i][j]);

    // Linear term: threads 0..63 each sum the bit count of one qubit column.
    if (tid < NQ) {
        int n1 = 0;
        #pragma unroll 8
        for (int ch = 0; ch < CHUNKS; ch++)
            n1 += __popc(col[ch][tid]);
        p += bias[tid] * (float)(NS - 2 * n1);
    }

    // Block reduction.
    red[tid] = p;
    __syncthreads();
    #pragma unroll
    for (int s = THREADS / 2; s > 0; s >>= 1) {
        if (tid < s) red[tid] += red[tid + s];
        __syncthreads();
    }
    if (tid == 0) g_unique[c] = red[0] * (1.0f / (float)NS);
}

// Gather per-circuit expectations back to the full batch.
__global__ void gather_kernel(const int* __restrict__ idx,
                              float* __restrict__ out)
{
    const int i = blockIdx.x * blockDim.x + threadIdx.x;
    if (i < NB) out[i] = g_unique[idx[i]];
}

extern "C" void kernel_launch(void* const* d_in, const int* in_sizes, int n_in,
                              void* d_out, int out_size)
{
    const int*   samples = (const int*)d_in[0];
    const int*   idx     = (const int*)d_in[1];
    const float* bias    = (const float*)d_in[2];
    const float* kern    = (const float*)d_in[3];
    float*       out     = (float*)d_out;

    energy_kernel<<<NU, THREADS>>>(samples, bias, kern);
    gather_kernel<<<(NB + 255) / 256, 256>>>(idx, out);
}

// round 2
// speedup vs baseline: 1.9426x; 1.9426x over previous
#include <cuda_runtime.h>
#include <cstdint>

// Problem constants (fixed by the reference)
#define NQ       64            // qubits
#define NS       4096          // samples per unique circuit
#define NU       256           // unique circuits
#define NB       1024          // batch size
#define PARTS    4             // blocks per circuit
#define NSB      (NS / PARTS)  // samples per block = 1024
#define CHUNKS_B (NSB / 32)    // 32 chunks of 32 samples
#define THREADS  256
#define NWARPS   (THREADS / 32)
#define CH_PER_WARP (CHUNKS_B / NWARPS)  // 4

// Per-(circuit,part) partial energy sums (NOT yet divided by NS).
__device__ float g_part[NU * PARTS];

// One block per (circuit, quarter). Phase 1 streams 256 KB of int32
// bitstrings with fully coalesced LDG.128, bit-transposes via warp ballots
// into per-qubit 32-bit column words in shared memory. Phase 2 does exact
// XOR-popcount pair counting on the upper triangle (K folded symmetrically).
__global__ void __launch_bounds__(THREADS)
energy_kernel(const int* __restrict__ samples,
              const float* __restrict__ bias,
              const float* __restrict__ kern)
{
    __shared__ uint32_t col[CHUNKS_B][NQ];   // [chunk][qubit] : 8 KB
    __shared__ float red[THREADS];

    const int tid  = threadIdx.x;
    const int lane = tid & 31;
    const int w    = tid >> 5;
    const int bx   = blockIdx.x;
    const int c    = bx >> 2;        // circuit
    const int part = bx & 3;         // quarter

    // uint4 view of this block's 1024 sample rows (16 uint4 per row).
    const uint4* base =
        (const uint4*)(samples + (size_t)c * (size_t)(NS * NQ))
        + (size_t)part * NSB * 16;

    // This lane owns qubits (lane) and (lane+32):
    //   qubit q = 4*p + b  with p = lane>>2 (0..7), b = lane&3.
    const int b = lane & 3;
    const int p = lane >> 2;

    // ---------------- Phase 1: coalesced load + ballot transpose ----------
    #pragma unroll 1
    for (int k = 0; k < CH_PER_WARP; k++) {
        const int ch = w * CH_PER_WARP + k;
        const uint4* P = base + (size_t)ch * 512;   // 32 rows * 16 uint4

        uint32_t colA = 0u, colB = 0u;
        #pragma unroll
        for (int j = 0; j < 16; j++) {
            // Coalesced: lanes read consecutive uint4.
            // lane l holds sample 2j + (l>>4), qubits 4*(l&15)..4*(l&15)+3.
            const uint4 v = P[j * 32 + lane];
            const uint32_t nib = (uint32_t)v.x | ((uint32_t)v.y << 1) |
                                 ((uint32_t)v.z << 2) | ((uint32_t)v.w << 3);

            const uint32_t W0 = __ballot_sync(0xffffffffu, nib & 1u);
            const uint32_t W1 = __ballot_sync(0xffffffffu, nib & 2u);
            const uint32_t W2 = __ballot_sync(0xffffffffu, nib & 4u);
            const uint32_t W3 = __ballot_sync(0xffffffffu, nib & 8u);

            // Select the ballot word for this lane's bit index b.
            const uint32_t Wl = (b & 1) ? W1 : W0;
            const uint32_t Wh = (b & 1) ? W3 : W2;
            const uint32_t Ws = (b & 2) ? Wh : Wl;

            // W bit layout: bit (16*(s-2j) + pp) = sample s, qubit 4*pp+b.
            const uint32_t t = Ws >> p;
            colA |= (t & 1u)          << (2 * j);      // qubit lane,    sample 2j
            colA |= ((t >> 16) & 1u)  << (2 * j + 1);  // qubit lane,    sample 2j+1
            colB |= ((t >> 8) & 1u)   << (2 * j);      // qubit lane+32, sample 2j
            colB |= ((t >> 24) & 1u)  << (2 * j + 1);  // qubit lane+32, sample 2j+1
        }
        col[ch][lane]      = colA;
        col[ch][lane + 32] = colB;
    }
    __syncthreads();

    // ---------------- Phase 2: triangular pair counting --------------------
    float acc = 0.f;

    if (tid < 136) {
        // Map tid -> upper-triangle tile (I <= J) of the 16x16 tile grid.
        int t = tid, I = 0;
        while (t >= 16 - I) { t -= 16 - I; I++; }
        const int J  = I + t;
        const int q0 = I << 2;
        const int r0 = J << 2;

        int cnt[4][4];
        #pragma unroll
        for (int i = 0; i < 4; i++)
            #pragma unroll
            for (int j = 0; j < 4; j++)
                cnt[i][j] = 0;

        #pragma unroll 4
        for (int ch = 0; ch < CHUNKS_B; ch++) {
            const uint4 a4 = *(const uint4*)&col[ch][q0];
            const uint4 b4 = *(const uint4*)&col[ch][r0];
            const uint32_t a[4]  = {a4.x, a4.y, a4.z, a4.w};
            const uint32_t bb[4] = {b4.x, b4.y, b4.z, b4.w};
            #pragma unroll
            for (int i = 0; i < 4; i++)
                #pragma unroll
                for (int j = 0; j < 4; j++)
                    cnt[i][j] += __popc(a[i] ^ bb[j]);
        }

        // Fold K. Off-diagonal tiles cover (q,r) AND (r,q) via symmetry of
        // the xor count; diagonal tiles are computed fully ordered.
        #pragma unroll
        for (int i = 0; i < 4; i++) {
            #pragma unroll
            for (int j = 0; j < 4; j++) {
                const int q = q0 + i, r = r0 + j;
                float kv = kern[q * NQ + r];
                if (I != J) kv += kern[r * NQ + q];
                acc += kv * (float)(NSB - 2 * cnt[i][j]);
            }
        }
    }

    // Linear term on otherwise-idle warps 6,7: one qubit column each.
    if (tid >= 192) {
        const int q = tid - 192;
        int n1 = 0;
        #pragma unroll 8
        for (int ch = 0; ch < CHUNKS_B; ch++)
            n1 += __popc(col[ch][q]);
        acc += bias[q] * (float)(NSB - 2 * n1);
    }

    // Block reduction.
    red[tid] = acc;
    __syncthreads();
    #pragma unroll
    for (int s = THREADS / 2; s > 0; s >>= 1) {
        if (tid < s) red[tid] += red[tid + s];
        __syncthreads();
    }
    if (tid == 0) g_part[bx] = red[0];
}

// Sum the 4 deterministic partials per circuit, normalize, gather to batch.
__global__ void gather_kernel(const int* __restrict__ idx,
                              float* __restrict__ out)
{
    const int i = blockIdx.x * blockDim.x + threadIdx.x;
    if (i < NB) {
        const int u = idx[i];
        const float s = g_part[4 * u + 0] + g_part[4 * u + 1] +
                        g_part[4 * u + 2] + g_part[4 * u + 3];
        out[i] = s * (1.0f / (float)NS);
    }
}

extern "C" void kernel_launch(void* const* d_in, const int* in_sizes, int n_in,
                              void* d_out, int out_size)
{
    const int*   samples = (const int*)d_in[0];
    const int*   idx     = (const int*)d_in[1];
    const float* bias    = (const float*)d_in[2];
    const float* kern    = (const float*)d_in[3];
    float*       out     = (float*)d_out;

    energy_kernel<<<NU * PARTS, THREADS>>>(samples, bias, kern);
    gather_kernel<<<(NB + 255) / 256, 256>>>(idx, out);
}

// round 3
// speedup vs baseline: 2.0609x; 1.0609x over previous
#include <cuda_runtime.h>
#include <cstdint>

// Problem constants (fixed by the reference)
#define NQ       64            // qubits
#define NS       4096          // samples per unique circuit
#define NU       256           // unique circuits
#define NB       1024          // batch size
#define PARTS    8             // blocks per circuit
#define NSB      (NS / PARTS)  // samples per block = 512
#define CHUNKS_B (NSB / 32)    // 16 chunks of 32 samples
#define THREADS  256
#define NWARPS   (THREADS / 32)
#define CH_PER_WARP (CHUNKS_B / NWARPS)  // 2
#define GRID     (NU * PARTS)  // 2048

// Per-(circuit,part) partial energy sums and completion counter.
__device__ float        g_part[GRID];
__device__ unsigned int g_count;   // zero-initialized; reset by last block

// One ballot-transpose step: lane owns qubits (lane) and (lane+32).
// Column bit order is (consistently) permuted vs sample order, which is
// irrelevant for XOR-popcount pair counting and column popcounts.
__device__ __forceinline__ void tstep(const uint4 v, const uint32_t b,
                                      const uint32_t p,
                                      uint32_t& colA, uint32_t& colB)
{
    const uint32_t nib = (uint32_t)v.x + ((uint32_t)v.y << 1) +
                         ((uint32_t)v.z << 2) + ((uint32_t)v.w << 3);
    const uint32_t W0 = __ballot_sync(0xffffffffu, nib & 1u);
    const uint32_t W1 = __ballot_sync(0xffffffffu, nib & 2u);
    const uint32_t W2 = __ballot_sync(0xffffffffu, nib & 4u);
    const uint32_t W3 = __ballot_sync(0xffffffffu, nib & 8u);
    const uint32_t Wl = (b & 1) ? W1 : W0;
    const uint32_t Wh = (b & 1) ? W3 : W2;
    const uint32_t Ws = (b & 2) ? Wh : Wl;
    const uint32_t t  = Ws >> p;
    // samples (2j, 2j+1) for qubit lane   live at t bits 0 and 16,
    //                    for qubit lane+32 at t bits 8 and 24.
    colA = (colA << 2) | (t & 1u)         | ((t >> 15) & 2u);
    colB = (colB << 2) | ((t >> 8) & 1u)  | ((t >> 23) & 2u);
}

// One block per (circuit, eighth). Single fused kernel:
//   Phase 1: coalesced LDG.128 stream + ballot bit-transpose into smem cols.
//   Phase 2: exact XOR-popcount pair counting, upper triangle, K folded.
//   Tail:    last finished block gathers all partials to the batch output.
__global__ void __launch_bounds__(THREADS)
energy_kernel(const int* __restrict__ samples,
              const int* __restrict__ idx,
              const float* __restrict__ bias,
              const float* __restrict__ kern,
              float* __restrict__ out)
{
    __shared__ uint32_t col[CHUNKS_B][NQ];   // 4 KB
    __shared__ float red[NWARPS];
    __shared__ bool s_last;

    const int tid  = threadIdx.x;
    const int lane = tid & 31;
    const int w    = tid >> 5;
    const int bx   = blockIdx.x;
    const int c    = bx >> 3;        // circuit
    const int part = bx & 7;         // eighth

    const uint4* base =
        (const uint4*)(samples + (size_t)c * (size_t)(NS * NQ))
        + (size_t)part * NSB * (NQ / 4);

    const uint32_t b = lane & 3;     // bit index within nibble
    const uint32_t p = lane >> 2;    // qubit group

    // ---------------- Phase 1: batched loads + ballot transpose ------------
    #pragma unroll
    for (int k = 0; k < CH_PER_WARP; k++) {
        const int ch = w * CH_PER_WARP + k;
        const uint4* P = base + (size_t)ch * 512;   // 32 rows * 16 uint4

        uint32_t colA = 0u, colB = 0u;
        uint4 v[8];

        #pragma unroll
        for (int j = 0; j < 8; j++) v[j] = P[j * 32 + lane];        // MLP=8
        #pragma unroll
        for (int j = 0; j < 8; j++) tstep(v[j], b, p, colA, colB);

        #pragma unroll
        for (int j = 0; j < 8; j++) v[j] = P[(j + 8) * 32 + lane];  // MLP=8
        #pragma unroll
        for (int j = 0; j < 8; j++) tstep(v[j], b, p, colA, colB);

        col[ch][lane]      = colA;
        col[ch][lane + 32] = colB;
    }
    __syncthreads();

    // ---------------- Phase 2: triangular pair counting --------------------
    float acc = 0.f;

    if (tid < 136) {
        // tid -> upper-triangle tile (I <= J) of the 16x16 tile grid.
        int t = tid, I = 0;
        while (t >= 16 - I) { t -= 16 - I; I++; }
        const int J  = I + t;
        const int q0 = I << 2;
        const int r0 = J << 2;

        int cnt[4][4];
        #pragma unroll
        for (int i = 0; i < 4; i++)
            #pragma unroll
            for (int j = 0; j < 4; j++)
                cnt[i][j] = 0;

        #pragma unroll 4
        for (int ch = 0; ch < CHUNKS_B; ch++) {
            const uint4 a4 = *(const uint4*)&col[ch][q0];
            const uint4 b4 = *(const uint4*)&col[ch][r0];
            const uint32_t a[4]  = {a4.x, a4.y, a4.z, a4.w};
            const uint32_t bb[4] = {b4.x, b4.y, b4.z, b4.w};
            #pragma unroll
            for (int i = 0; i < 4; i++)
                #pragma unroll
                for (int j = 0; j < 4; j++)
                    cnt[i][j] += __popc(a[i] ^ bb[j]);
        }

        #pragma unroll
        for (int i = 0; i < 4; i++) {
            #pragma unroll
            for (int j = 0; j < 4; j++) {
                const int q = q0 + i, r = r0 + j;
                float kv = kern[q * NQ + r];
                if (I != J) kv += kern[r * NQ + q];
                acc += kv * (float)(NSB - 2 * cnt[i][j]);
            }
        }
    }

    // Linear term on otherwise-idle warps 6,7.
    if (tid >= 192) {
        const int q = tid - 192;
        int n1 = 0;
        #pragma unroll
        for (int ch = 0; ch < CHUNKS_B; ch++)
            n1 += __popc(col[ch][q]);
        acc += bias[q] * (float)(NSB - 2 * n1);
    }

    // ---------------- Reduction + fused gather ----------------------------
    #pragma unroll
    for (int o = 16; o > 0; o >>= 1)
        acc += __shfl_down_sync(0xffffffffu, acc, o);
    if (lane == 0) red[w] = acc;
    __syncthreads();

    if (tid == 0) {
        float s = 0.f;
        #pragma unroll
        for (int i = 0; i < NWARPS; i++) s += red[i];
        g_part[bx] = s;
        __threadfence();
        const unsigned int done = atomicAdd(&g_count, 1u);
        s_last = (done == GRID - 1);
    }
    __syncthreads();

    if (s_last) {
        __threadfence();
        for (int i = tid; i < NB; i += THREADS) {
            const int u = idx[i];
            const float* gp = &g_part[u * PARTS];
            float s = 0.f;
            #pragma unroll
            for (int q = 0; q < PARTS; q++) s += gp[q];
            out[i] = s * (1.0f / (float)NS);
        }
        if (tid == 0) g_count = 0u;   // reset for next graph replay
    }
}

extern "C" void kernel_launch(void* const* d_in, const int* in_sizes, int n_in,
                              void* d_out, int out_size)
{
    const int*   samples = (const int*)d_in[0];
    const int*   idx     = (const int*)d_in[1];
    const float* bias    = (const float*)d_in[2];
    const float* kern    = (const float*)d_in[3];
    float*       out     = (float*)d_out;

    energy_kernel<<<GRID, THREADS>>>(samples, idx, bias, kern, out);
}